// round 5
// baseline (speedup 1.0000x reference)
#include <cuda_runtime.h>
#include <cuda_bf16.h>

// out[i,j,:] = W[d_res] + W[66+d_tok] + same_entity*W[132] + W[133+d_chain]
//
// d_res   = same_chain ? clip(res_i-res_j+32, 0, 64)              : 65
// d_tok   = same_chain && res_i==res_j ? clip(tok_i-tok_j+32,0,64): 65
// d_chain = !same_chain ? clip(sym_i-sym_j+2, 0, 4)               : 5
//
// Structural fast paths (exact, not data-dependent heuristics):
//  - !same_chain  -> rows 65 and 131 are fixed: precomputed register sum. 1 LDS.
//  - same_chain   -> chain row is fixed 138: register.                    2 LDS.
//  - entity row 132: register, added under predicate.

#define RMAX 32
#define SMAX 2

__device__ __forceinline__ float4 f4add(float4 a, float4 b) {
    return make_float4(a.x + b.x, a.y + b.y, a.z + b.z, a.w + b.w);
}

__global__ __launch_bounds__(256) void relpos_kernel(
    const float* __restrict__ feats,   // [n, 10]
    const float* __restrict__ W,       // [139, 128]
    float* __restrict__ out,           // [n, n, 128]
    int n)
{
    extern __shared__ float4 Wsm[];    // 139 rows * 32 float4 = 71168 B
    const int tid  = threadIdx.x;
    const int lane = tid & 31;
    const int wpr  = tid >> 5;         // warp id in block = pair slot
    const int npr  = blockDim.x >> 5;  // pairs per iteration (8)

    // Cooperative load of all 139 W rows into smem (float4 granularity).
    const float4* Wg4 = (const float4*)W;
    for (int idx = tid; idx < 139 * 32; idx += blockDim.x)
        Wsm[idx] = Wg4[idx];

    // Per-lane register-resident fixed rows / sums (chunk = lane).
    const float4 w132 = Wg4[132 * 32 + lane];                       // entity row
    const float4 w138 = Wg4[138 * 32 + lane];                       // chain row when same_chain (d_chain=5)
    const float4 s_xc = f4add(Wg4[65 * 32 + lane],
                              Wg4[131 * 32 + lane]);                // W[65]+W[131]: cross-chain res+tok rows

    const int i = blockIdx.x;
    const float* fi = feats + (size_t)i * 10;
    const int ri = (int)fi[0], ti = (int)fi[1], ai = (int)fi[2],
              ei = (int)fi[3], si = (int)fi[4];

    __syncthreads();

    float4* out4 = (float4*)out + (size_t)i * n * 32;

    for (int j = wpr; j < n; j += npr) {
        const float* fj = feats + (size_t)j * 10;
        const int rj = (int)__ldg(fj + 0);
        const int tj = (int)__ldg(fj + 1);
        const int aj = (int)__ldg(fj + 2);
        const int ej = (int)__ldg(fj + 3);
        const int sj = (int)__ldg(fj + 4);

        const bool same_chain = (ai == aj);
        float4 v;
        if (same_chain) {
            const int dr    = ri - rj;
            const int d_res = min(max(dr + RMAX, 0), 2 * RMAX);
            const int d_tok = (dr == 0) ? min(max(ti - tj + RMAX, 0), 2 * RMAX)
                                        : 2 * RMAX + 1;
            float4 a = Wsm[d_res * 32 + lane];
            float4 b = Wsm[(66 + d_tok) * 32 + lane];
            v = f4add(f4add(a, b), w138);
        } else {
            const int d_chain = min(max(si - sj + SMAX, 0), 2 * SMAX);
            float4 c = Wsm[(133 + d_chain) * 32 + lane];
            v = f4add(s_xc, c);
        }
        if (ei == ej) v = f4add(v, w132);

        out4[(size_t)j * 32 + lane] = v;
    }
}

extern "C" void kernel_launch(void* const* d_in, const int* in_sizes, int n_in,
                              void* d_out, int out_size)
{
    const float* feats = (const float*)d_in[0];   // [b=1, n, 10] float32
    const float* W     = (const float*)d_in[1];   // [139, 128]   float32
    float* out         = (float*)d_out;           // [1, n, n, 128] float32

    const int n = in_sizes[0] / 10;               // b = 1
    const size_t smem = 139 * 128 * sizeof(float);// 71168 B > 48K -> opt-in

    cudaFuncSetAttribute(relpos_kernel,
                         cudaFuncAttributeMaxDynamicSharedMemorySize,
                         (int)smem);

    relpos_kernel<<<n, 256, smem>>>(feats, W, out, n);
}

// round 6
// speedup vs baseline: 2.7070x; 2.7070x over previous
#include <cuda_runtime.h>
#include <cuda_bf16.h>

// out[i,j,:] = W[d_res] + W[66+d_tok] + same_entity*W[132] + W[133+d_chain]
//
// d_res   = same_chain ? clip(res_i-res_j+32, 0, 64)               : 65
// d_tok   = same_chain && res_i==res_j ? clip(tok_i-tok_j+32,0,64) : 65
// d_chain = !same_chain ? clip(sym_i-sym_j+2, 0, 4)                : 5
//
// feats are random ints 0..63 -> same_chain holds for ~1.6% of pairs.
// Hot (cross-chain) path: value is one of only 10 vectors
//     tab[c + 5e] = W[65]+W[131]+W[133+c] + e*W[132]   (c in 0..4, e in {0,1})
// -> per-block 5 KB smem table, one LDS.128 per pair.
// Rare (same-chain) path: gather W rows straight from L2 (__ldg).
// All per-j decision logic hoisted into a per-block prologue (packed[j]).

__device__ __forceinline__ float4 f4add(float4 a, float4 b) {
    return make_float4(a.x + b.x, a.y + b.y, a.z + b.z, a.w + b.w);
}

__global__ __launch_bounds__(256) void relpos_kernel(
    const float* __restrict__ feats,   // [n, 10]
    const float* __restrict__ W,       // [139, 128]
    float* __restrict__ out,           // [n, n, 128]
    int n)
{
    extern __shared__ char smem_raw[];
    float4* tab   = (float4*)smem_raw;                        // 10 * 32 float4 = 5120 B
    int*    packd = (int*)(smem_raw + 10 * 128 * sizeof(float)); // n ints

    const int tid = threadIdx.x;
    const int i   = blockIdx.x;

    // Row-i features (uniform across block; tiny L2-resident reads).
    const float* fi = feats + (size_t)i * 10;
    const int ri = (int)fi[0], ti = (int)fi[1], ai = (int)fi[2],
              ei = (int)fi[3], si = (int)fi[4];

    // ---- Prologue 1: build the 10 combined cross-chain vectors -------------
    for (int idx = tid; idx < 10 * 128; idx += blockDim.x) {
        const int r = idx >> 7;        // 0..9
        const int c = idx & 127;
        float v = __ldg(W +  65 * 128 + c)
                + __ldg(W + 131 * 128 + c)
                + __ldg(W + (133 + (r % 5)) * 128 + c);
        if (r >= 5) v += __ldg(W + 132 * 128 + c);   // same-entity variant
        ((float*)tab)[idx] = v;
    }

    // ---- Prologue 2: per-j packed decision ---------------------------------
    for (int j = tid; j < n; j += blockDim.x) {
        const float* fj = feats + (size_t)j * 10;
        const int rj = (int)__ldg(fj + 0);
        const int tj = (int)__ldg(fj + 1);
        const int aj = (int)__ldg(fj + 2);
        const int ej = (int)__ldg(fj + 3);
        const int sj = (int)__ldg(fj + 4);
        const int e  = (ei == ej) ? 1 : 0;

        int p;
        if (ai == aj) {                       // rare same-chain path
            const int dr    = ri - rj;
            const int d_res = min(max(dr + 32, 0), 64);
            const int d_tok = (dr == 0) ? min(max(ti - tj + 32, 0), 64) : 65;
            p = (int)0x80000000 | (e << 14) | (d_tok << 7) | d_res;
        } else {                              // hot path: table index 0..9
            const int d_chain = min(max(si - sj + 2, 0), 4);
            p = d_chain + 5 * e;
        }
        packd[j] = p;
    }
    __syncthreads();

    // ---- Main loop: warp-per-pair ------------------------------------------
    const int lane = tid & 31;
    const int wpr  = tid >> 5;
    const int npr  = blockDim.x >> 5;

    float4* out4 = (float4*)out + (size_t)i * n * 32;
    const float4* Wg4 = (const float4*)W;

    for (int j = wpr; j < n; j += npr) {
        const int p = packd[j];              // warp-uniform scalar LDS
        float4 v;
        if (p >= 0) {
            v = tab[p * 32 + lane];          // one LDS.128, conflict-free
        } else {
            const int d_res = p & 127;
            const int d_tok = (p >> 7) & 127;
            float4 a = Wg4[d_res * 32 + lane];
            float4 b = Wg4[(66 + d_tok) * 32 + lane];
            float4 c = Wg4[138 * 32 + lane];
            v = f4add(f4add(a, b), c);
            if ((p >> 14) & 1) v = f4add(v, Wg4[132 * 32 + lane]);
        }
        out4[(size_t)j * 32 + lane] = v;     // STG.128, 512B/warp coalesced
    }
}

extern "C" void kernel_launch(void* const* d_in, const int* in_sizes, int n_in,
                              void* d_out, int out_size)
{
    const float* feats = (const float*)d_in[0];   // [1, n, 10] float32
    const float* W     = (const float*)d_in[1];   // [139, 128] float32
    float* out         = (float*)d_out;           // [1, n, n, 128] float32

    const int n = in_sizes[0] / 10;               // b = 1
    const size_t smem = 10 * 128 * sizeof(float) + (size_t)n * sizeof(int);

    if (smem > 48 * 1024) {
        cudaFuncSetAttribute(relpos_kernel,
                             cudaFuncAttributeMaxDynamicSharedMemorySize,
                             (int)smem);
    }
    relpos_kernel<<<n, 256, smem>>>(feats, W, out, n);
}

// round 10
// speedup vs baseline: 2.7185x; 1.0042x over previous
#include <cuda_runtime.h>
#include <cuda_bf16.h>

// out[i,j,:] = W[d_res] + W[66+d_tok] + same_entity*W[132] + W[133+d_chain]
//
// Cross-chain (~98.4% of pairs): value is one of 10 vectors
//     tab[c + 5e] = W[65]+W[131]+W[133+c] + e*W[132]
// and because sym ids are broad, d_chain saturates: p==0 or p==4 for ~95%
// of ALL pairs -> keep tab[0], tab[4] in registers; LDS only for the rest.
// Same-chain (~1.6%): gather W rows from L2 via __ldg.
// Streaming __stcs stores (write-once 537MB output, don't pollute L2).

__device__ __forceinline__ float4 f4add(float4 a, float4 b) {
    return make_float4(a.x + b.x, a.y + b.y, a.z + b.z, a.w + b.w);
}

__global__ __launch_bounds__(256) void relpos_kernel(
    const float* __restrict__ feats,   // [n, 10]
    const float* __restrict__ W,       // [139, 128]
    float* __restrict__ out,           // [n, n, 128]
    int n)
{
    extern __shared__ char smem_raw[];
    float4* tab   = (float4*)smem_raw;                           // 10*32 float4 = 5120 B
    int*    packd = (int*)(smem_raw + 10 * 128 * sizeof(float)); // n ints

    const int tid = threadIdx.x;
    const int i   = blockIdx.x;

    const float* fi = feats + (size_t)i * 10;
    const int ri = (int)fi[0], ti = (int)fi[1], ai = (int)fi[2],
              ei = (int)fi[3], si = (int)fi[4];

    // ---- Prologue 1: the 10 combined cross-chain vectors -------------------
    for (int idx = tid; idx < 10 * 128; idx += blockDim.x) {
        const int r = idx >> 7;        // 0..9
        const int c = idx & 127;
        float v = __ldg(W +  65 * 128 + c)
                + __ldg(W + 131 * 128 + c)
                + __ldg(W + (133 + (r % 5)) * 128 + c);
        if (r >= 5) v += __ldg(W + 132 * 128 + c);   // same-entity variant
        ((float*)tab)[idx] = v;
    }

    // ---- Prologue 2: per-j packed decision ---------------------------------
    for (int j = tid; j < n; j += blockDim.x) {
        const float* fj = feats + (size_t)j * 10;
        const int rj = (int)__ldg(fj + 0);
        const int tj = (int)__ldg(fj + 1);
        const int aj = (int)__ldg(fj + 2);
        const int ej = (int)__ldg(fj + 3);
        const int sj = (int)__ldg(fj + 4);
        const int e  = (ei == ej) ? 1 : 0;

        int p;
        if (ai == aj) {                       // rare same-chain path
            const int dr    = ri - rj;
            const int d_res = min(max(dr + 32, 0), 64);
            const int d_tok = (dr == 0) ? min(max(ti - tj + 32, 0), 64) : 65;
            p = (int)0x80000000 | (e << 14) | (d_tok << 7) | d_res;
        } else {                              // hot path: table index 0..9
            const int d_chain = min(max(si - sj + 2, 0), 4);
            p = d_chain + 5 * e;
        }
        packd[j] = p;
    }
    __syncthreads();

    // ---- Main loop: warp-per-pair, contiguous per-warp chunks --------------
    const int lane = tid & 31;
    const int wpr  = tid >> 5;
    const int npr  = blockDim.x >> 5;         // 8 warps

    const int chunk = (n + npr - 1) / npr;    // 128 for n=1024
    const int j0 = wpr * chunk;
    const int j1 = min(j0 + chunk, n);

    // Register-resident dominant vectors (p==0 and p==4 cover ~95% of pairs).
    const float4 v0 = tab[0 * 32 + lane];
    const float4 v4 = tab[4 * 32 + lane];

    float4* out4 = (float4*)out + (size_t)i * n * 32;
    const float4* Wg4 = (const float4*)W;

    #pragma unroll 4
    for (int j = j0; j < j1; ++j) {
        const int p = packd[j];               // warp-uniform broadcast LDS
        float4 v;
        if (p == 0)      v = v0;
        else if (p == 4) v = v4;
        else if (p >= 0) v = tab[p * 32 + lane];
        else {                                // rare same-chain gather from L2
            const int d_res = p & 127;
            const int d_tok = (p >> 7) & 127;
            float4 a = Wg4[d_res * 32 + lane];
            float4 b = Wg4[(66 + d_tok) * 32 + lane];
            float4 c = Wg4[138 * 32 + lane];
            v = f4add(f4add(a, b), c);
            if ((p >> 14) & 1) v = f4add(v, Wg4[132 * 32 + lane]);
        }
        __stcs(&out4[(size_t)j * 32 + lane], v);   // streaming STG.128
    }
}

extern "C" void kernel_launch(void* const* d_in, const int* in_sizes, int n_in,
                              void* d_out, int out_size)
{
    const float* feats = (const float*)d_in[0];   // [1, n, 10] float32
    const float* W     = (const float*)d_in[1];   // [139, 128] float32
    float* out         = (float*)d_out;           // [1, n, n, 128] float32

    const int n = in_sizes[0] / 10;               // b = 1
    const size_t smem = 10 * 128 * sizeof(float) + (size_t)n * sizeof(int);

    if (smem > 48 * 1024) {
        cudaFuncSetAttribute(relpos_kernel,
                             cudaFuncAttributeMaxDynamicSharedMemorySize,
                             (int)smem);
    }
    relpos_kernel<<<n, 256, smem>>>(feats, W, out, n);
}